// round 4
// baseline (speedup 1.0000x reference)
#include <cuda_runtime.h>
#include <cuda_bf16.h>
#include <math.h>
#include <stdint.h>

#define B_TOTAL 16384
#define F_DIM   512
#define P_DIM   128
#define C_DIM   10

#define BM   128
#define BK   64
#define TPB  256
#define PITCH 72          // bf16 pitch of GEMM smem tiles (conflict-free frag loads)
#define SIP  130          // float pitch of si tile (conflict-free epilogue scatter)

// ---------------- device-global precomputed tensors ----------------
__device__ __align__(16) __nv_bfloat16 g_wh[P_DIM * F_DIM];
__device__ __align__(16) __nv_bfloat16 g_wl[P_DIM * F_DIM];
__device__ float g_wsq[P_DIM];
__device__ float g_gamma[P_DIM];
__device__ float g_alpha[P_DIM];
__device__ float g_u[C_DIM * P_DIM];   // [c][p]

// ---------------- helpers ----------------
__device__ __forceinline__ unsigned pk2(float a, float b) {
    __nv_bfloat162 t;
    t.x = __float2bfloat16_rn(a);
    t.y = __float2bfloat16_rn(b);
    return *reinterpret_cast<unsigned*>(&t);
}

__device__ __forceinline__ void cp16(unsigned dst, const void* src) {
    asm volatile("cp.async.ca.shared.global [%0], [%1], 16;\n" :: "r"(dst), "l"(src));
}
__device__ __forceinline__ void cp_commit() { asm volatile("cp.async.commit_group;\n"); }
__device__ __forceinline__ void cp_wait0()  { asm volatile("cp.async.wait_group 0;\n"); }

__device__ __forceinline__ void mma16816(float* c, const unsigned* a, const unsigned* b) {
    asm volatile(
        "mma.sync.aligned.m16n8k16.row.col.f32.bf16.bf16.f32 "
        "{%0,%1,%2,%3}, {%4,%5,%6,%7}, {%8,%9}, {%0,%1,%2,%3};\n"
        : "+f"(c[0]), "+f"(c[1]), "+f"(c[2]), "+f"(c[3])
        : "r"(a[0]), "r"(a[1]), "r"(a[2]), "r"(a[3]), "r"(b[0]), "r"(b[1]));
}

// ---------------- precompute kernel ----------------
__global__ void ds_precomp(const float* __restrict__ w,
                           const float* __restrict__ eta,
                           const float* __restrict__ xi,
                           const float* __restrict__ beta) {
    int p = threadIdx.x;
    if (p >= P_DIM) return;
    float s = 0.f;
#pragma unroll 8
    for (int i = 0; i < F_DIM; ++i) {
        float f = w[(size_t)p * F_DIM + i];
        s = fmaf(f, f, s);
        __nv_bfloat16 hi = __float2bfloat16_rn(f);
        float lo = f - __bfloat162float(hi);
        g_wh[(size_t)p * F_DIM + i] = hi;
        g_wl[(size_t)p * F_DIM + i] = __float2bfloat16_rn(lo);
    }
    g_wsq[p] = s;
    float e = eta[p];
    g_gamma[p] = e * e;
    g_alpha[p] = 1.f / (1.f + expf(-xi[p]));
    float b2[C_DIM];
    float bs = 0.f;
#pragma unroll
    for (int c = 0; c < C_DIM; ++c) {
        float b = beta[c * P_DIM + p];
        b2[c] = b * b;
        bs += b2[c];
    }
    float inv = 1.f / bs;
#pragma unroll
    for (int c = 0; c < C_DIM; ++c) g_u[c * P_DIM + p] = b2[c] * inv;
}

// ---------------- smem layout (bytes) ----------------
// GEMM phase:
//   SXH [2][128][72] bf16 @ 0        (36864 B)
//   SXL                  @ 36864
//   SWH                  @ 73728
//   SWL                  @ 110592    (ends 147456)
// post-GEMM (union with GEMM region):
//   si [128 p][130 b] float @ 0      (66560 B)
// persistent:
//   us  [10][128] float  @ 147456    (5120 B)
//   xns [128]   float    @ 152576
//   xnp [256]   float    @ 153088
#define OFF_SXL 36864
#define OFF_SWH 73728
#define OFF_SWL 110592
#define OFF_US  147456
#define OFF_XNS 152576
#define OFF_XNP 153088
#define SMEM_BYTES 154112
#define STAGE_B 18432     // bytes per stage within each array

__global__ void __launch_bounds__(TPB, 1)
ds_main(const float* __restrict__ x, float* __restrict__ out) {
    extern __shared__ char smem[];
    __nv_bfloat16* sxh = (__nv_bfloat16*)(smem);
    __nv_bfloat16* sxl = (__nv_bfloat16*)(smem + OFF_SXL);
    __nv_bfloat16* swh = (__nv_bfloat16*)(smem + OFF_SWH);
    __nv_bfloat16* swl = (__nv_bfloat16*)(smem + OFF_SWL);
    float* si  = (float*)smem;
    float* us  = (float*)(smem + OFF_US);
    float* xns = (float*)(smem + OFF_XNS);
    float* xnp = (float*)(smem + OFF_XNP);
    unsigned sm_u32 = (unsigned)__cvta_generic_to_shared(smem);

    const int tid  = threadIdx.x;
    const int lane = tid & 31;
    const int wid  = tid >> 5;
    const int row0 = blockIdx.x * BM;

    // stage u into smem
    for (int i = tid; i < C_DIM * P_DIM; i += TPB) us[i] = g_u[i];

    // load/convert role: thread owns row r, k-half kh
    const int lr = tid >> 1;
    const int lkh = (tid & 1) * 32;
    const float* xblk = x + (size_t)row0 * F_DIM;

    float acc[2][8][4];
#pragma unroll
    for (int mt = 0; mt < 2; ++mt)
#pragma unroll
        for (int nt = 0; nt < 8; ++nt)
#pragma unroll
            for (int e = 0; e < 4; ++e) acc[mt][nt][e] = 0.f;

    float xn = 0.f;
    float4 xv[8];

    // ---- w tile issue (cp.async) ----
    auto issue_w = [&](int kt, int s) {
        const __nv_bfloat16* sH = g_wh + (size_t)lr * F_DIM + kt * BK + lkh;
        const __nv_bfloat16* sL = g_wl + (size_t)lr * F_DIM + kt * BK + lkh;
        unsigned dH = sm_u32 + OFF_SWH + s * STAGE_B + (lr * PITCH + lkh) * 2;
        unsigned dL = sm_u32 + OFF_SWL + s * STAGE_B + (lr * PITCH + lkh) * 2;
#pragma unroll
        for (int j = 0; j < 4; ++j) {
            cp16(dH + 16 * j, sH + 8 * j);
            cp16(dL + 16 * j, sL + 8 * j);
        }
        cp_commit();
    };
    // ---- x tile global load ----
    auto ldx = [&](int kt) {
        const float* p = xblk + (size_t)lr * F_DIM + kt * BK + lkh;
#pragma unroll
        for (int j = 0; j < 8; ++j) xv[j] = *(const float4*)(p + 4 * j);
    };
    // ---- x tile split/convert + smem store (+ ||x||^2) ----
    auto stx = [&](int s) {
        __nv_bfloat16* dh = sxh + s * (STAGE_B / 2) + lr * PITCH + lkh;
        __nv_bfloat16* dl = sxl + s * (STAGE_B / 2) + lr * PITCH + lkh;
#pragma unroll
        for (int j = 0; j < 8; ++j) {
            float f0 = xv[j].x, f1 = xv[j].y, f2 = xv[j].z, f3 = xv[j].w;
            xn = fmaf(f0, f0, xn); xn = fmaf(f1, f1, xn);
            xn = fmaf(f2, f2, xn); xn = fmaf(f3, f3, xn);
            __nv_bfloat16 h0 = __float2bfloat16_rn(f0), h1 = __float2bfloat16_rn(f1);
            __nv_bfloat16 h2 = __float2bfloat16_rn(f2), h3 = __float2bfloat16_rn(f3);
            uint2 hv, lv;
            hv.x = pk2(f0, f1); hv.y = pk2(f2, f3);
            lv.x = pk2(f0 - __bfloat162float(h0), f1 - __bfloat162float(h1));
            lv.y = pk2(f2 - __bfloat162float(h2), f3 - __bfloat162float(h3));
            *(uint2*)(dh + 4 * j) = hv;
            *(uint2*)(dl + 4 * j) = lv;
        }
    };

    const int wm = (wid & 3) * 32;
    const int wn = (wid >> 2) * 64;
    const int lq  = lane >> 2;
    const int lr2 = (lane & 3) * 2;

    // ---- compute one BK tile from stage s ----
    auto compute = [&](int s) {
        const __nv_bfloat16* bxh = sxh + s * (STAGE_B / 2);
        const __nv_bfloat16* bxl = sxl + s * (STAGE_B / 2);
        const __nv_bfloat16* bwh = swh + s * (STAGE_B / 2);
        const __nv_bfloat16* bwl = swl + s * (STAGE_B / 2);
#pragma unroll
        for (int kk = 0; kk < BK; kk += 16) {
            unsigned ah[2][4], al[2][4];
#pragma unroll
            for (int mt = 0; mt < 2; ++mt) {
                int base = (wm + mt * 16 + lq) * PITCH + kk + lr2;
                ah[mt][0] = *(const unsigned*)(bxh + base);
                ah[mt][1] = *(const unsigned*)(bxh + base + 8 * PITCH);
                ah[mt][2] = *(const unsigned*)(bxh + base + 8);
                ah[mt][3] = *(const unsigned*)(bxh + base + 8 * PITCH + 8);
                al[mt][0] = *(const unsigned*)(bxl + base);
                al[mt][1] = *(const unsigned*)(bxl + base + 8 * PITCH);
                al[mt][2] = *(const unsigned*)(bxl + base + 8);
                al[mt][3] = *(const unsigned*)(bxl + base + 8 * PITCH + 8);
            }
#pragma unroll
            for (int nt = 0; nt < 8; ++nt) {
                int nb = (wn + nt * 8 + lq) * PITCH + kk + lr2;
                unsigned bh[2], bl[2];
                bh[0] = *(const unsigned*)(bwh + nb);
                bh[1] = *(const unsigned*)(bwh + nb + 8);
                bl[0] = *(const unsigned*)(bwl + nb);
                bl[1] = *(const unsigned*)(bwl + nb + 8);
#pragma unroll
                for (int mt = 0; mt < 2; ++mt) {
                    mma16816(acc[mt][nt], ah[mt], bh);
                    mma16816(acc[mt][nt], al[mt], bh);
                    mma16816(acc[mt][nt], ah[mt], bl);
                }
            }
        }
    };

    // ---- pipelined main loop ----
    issue_w(0, 0);
    ldx(0);
    stx(0);
    cp_wait0();
    __syncthreads();

    for (int kt = 0; kt < F_DIM / BK; ++kt) {
        int cur = kt & 1;
        if (kt < F_DIM / BK - 1) {
            issue_w(kt + 1, 1 - cur);
            ldx(kt + 1);
        }
        compute(cur);
        if (kt < F_DIM / BK - 1) stx(1 - cur);
        cp_wait0();
        __syncthreads();
    }

    // ---- ||x||^2 reduction ----
    xnp[tid] = xn;
    __syncthreads();
    if (tid < BM) xns[tid] = xnp[2 * tid] + xnp[2 * tid + 1];
    __syncthreads();

    // ---- epilogue: d -> si[p][b] ----
    {
        float xnv[4];
#pragma unroll
        for (int mt = 0; mt < 2; ++mt) {
            xnv[mt * 2 + 0] = xns[wm + mt * 16 + lq];
            xnv[mt * 2 + 1] = xns[wm + mt * 16 + lq + 8];
        }
#pragma unroll
        for (int nt = 0; nt < 8; ++nt) {
            int cb = wn + nt * 8 + lr2;
            float ws0 = g_wsq[cb],   ws1 = g_wsq[cb + 1];
            float ga0 = g_gamma[cb], ga1 = g_gamma[cb + 1];
            float al0 = g_alpha[cb], al1 = g_alpha[cb + 1];
#pragma unroll
            for (int mt = 0; mt < 2; ++mt) {
                int r0 = wm + mt * 16 + lq;
                int r1 = r0 + 8;
                const float* a = acc[mt][nt];
                float d00 = xnv[mt * 2]     + ws0 - 2.f * a[0];
                float d01 = xnv[mt * 2]     + ws1 - 2.f * a[1];
                float d10 = xnv[mt * 2 + 1] + ws0 - 2.f * a[2];
                float d11 = xnv[mt * 2 + 1] + ws1 - 2.f * a[3];
                si[cb * SIP + r0]       = al0 * __expf(-ga0 * d00);
                si[(cb + 1) * SIP + r0] = al1 * __expf(-ga1 * d01);
                si[cb * SIP + r1]       = al0 * __expf(-ga0 * d10);
                si[(cb + 1) * SIP + r1] = al1 * __expf(-ga1 * d11);
            }
        }
    }
    __syncthreads();

    // ---- Dempster scan: one thread per batch row ----
    if (tid < BM) {
        const int r = tid;
        float mx = 0.f;
        for (int p = 0; p < P_DIM; ++p) mx = fmaxf(mx, si[p * SIP + r]);
        const float sinv = 1.f / (mx + 1e-4f);

        float s = si[r] * sinv;
        float m[C_DIM];
#pragma unroll
        for (int k = 0; k < C_DIM; ++k) m[k] = us[k * P_DIM + 0] * s;
        float o = 1.f - s;

        for (int p = 1; p < P_DIM; ++p) {
            s = si[p * SIP + r] * sinv;
            float om = 1.f - s;
            float os = o * s;
#pragma unroll
            for (int k = 0; k < C_DIM; ++k) {
                float u = us[k * P_DIM + p];
                float t = fmaf(s, u, om);        // 1 - s + s*u
                m[k] = fmaf(m[k], t, os * u);
            }
            o = 3.f * o * om;                    // c_omega = 3*o1*o2
            if ((p & 7) == 7) {                  // scale-invariant renorm
                float ssum = o;
#pragma unroll
                for (int k = 0; k < C_DIM; ++k) ssum += m[k];
                float rinv = 1.f / ssum;
#pragma unroll
                for (int k = 0; k < C_DIM; ++k) m[k] *= rinv;
                o *= rinv;
            }
        }
        float ssum = o;
#pragma unroll
        for (int k = 0; k < C_DIM; ++k) ssum += m[k];
        float rinv = 1.f / ssum;
        float* op = out + (size_t)(row0 + r) * (C_DIM + 1);
#pragma unroll
        for (int k = 0; k < C_DIM; ++k) op[k] = m[k] * rinv;
        op[C_DIM] = o * rinv;
    }
}

// ---------------- launch ----------------
extern "C" void kernel_launch(void* const* d_in, const int* in_sizes, int n_in,
                              void* d_out, int out_size) {
    const float* x    = (const float*)d_in[0];
    const float* w    = (const float*)d_in[1];
    const float* eta  = (const float*)d_in[2];
    const float* xi   = (const float*)d_in[3];
    const float* beta = (const float*)d_in[4];
    float* out = (float*)d_out;

    ds_precomp<<<1, P_DIM>>>(w, eta, xi, beta);

    cudaFuncSetAttribute(ds_main, cudaFuncAttributeMaxDynamicSharedMemorySize,
                         SMEM_BYTES);
    ds_main<<<B_TOTAL / BM, TPB, SMEM_BYTES>>>(x, out);
}

// round 5
// speedup vs baseline: 1.7443x; 1.7443x over previous
#include <cuda_runtime.h>
#include <cuda_bf16.h>
#include <math.h>
#include <stdint.h>

#define B_TOTAL 16384
#define F_DIM   512
#define P_DIM   128
#define C_DIM   10

#define BM   128
#define BK   64
#define TPB  256
#define PITCH 72          // bf16 pitch of GEMM smem tiles (conflict-free frag loads)
#define SIP  130          // float pitch of si tile (conflict-free epilogue scatter)

// ---------------- device-global precomputed tensors ----------------
__device__ __align__(16) __nv_bfloat16 g_wh[P_DIM * F_DIM];
__device__ __align__(16) __nv_bfloat16 g_wl[P_DIM * F_DIM];
__device__ float g_wsq[P_DIM];
__device__ float g_gamma[P_DIM];
__device__ float g_alpha[P_DIM];
__device__ float g_u[C_DIM * P_DIM];   // [c][p]

// ---------------- helpers ----------------
__device__ __forceinline__ unsigned pk2(float a, float b) {
    __nv_bfloat162 t;
    t.x = __float2bfloat16_rn(a);
    t.y = __float2bfloat16_rn(b);
    return *reinterpret_cast<unsigned*>(&t);
}

__device__ __forceinline__ void cp16(unsigned dst, const void* src) {
    asm volatile("cp.async.ca.shared.global [%0], [%1], 16;\n" :: "r"(dst), "l"(src));
}
__device__ __forceinline__ void cp_commit() { asm volatile("cp.async.commit_group;\n"); }
__device__ __forceinline__ void cp_wait0()  { asm volatile("cp.async.wait_group 0;\n"); }

__device__ __forceinline__ void mma16816(float* c, const unsigned* a, const unsigned* b) {
    asm volatile(
        "mma.sync.aligned.m16n8k16.row.col.f32.bf16.bf16.f32 "
        "{%0,%1,%2,%3}, {%4,%5,%6,%7}, {%8,%9}, {%0,%1,%2,%3};\n"
        : "+f"(c[0]), "+f"(c[1]), "+f"(c[2]), "+f"(c[3])
        : "r"(a[0]), "r"(a[1]), "r"(a[2]), "r"(a[3]), "r"(b[0]), "r"(b[1]));
}

// ---------------- precompute kernel A: split w into hi/lo bf16 (parallel) ----------------
// 64 blocks x 256 threads, one float4 per thread
__global__ void ds_split_w(const float* __restrict__ w) {
    int i = blockIdx.x * 256 + threadIdx.x;   // 0 .. 16383 float4s
    float4 v = ((const float4*)w)[i];
    __nv_bfloat16 h0 = __float2bfloat16_rn(v.x), h1 = __float2bfloat16_rn(v.y);
    __nv_bfloat16 h2 = __float2bfloat16_rn(v.z), h3 = __float2bfloat16_rn(v.w);
    uint2 hv, lv;
    hv.x = pk2(v.x, v.y); hv.y = pk2(v.z, v.w);
    lv.x = pk2(v.x - __bfloat162float(h0), v.y - __bfloat162float(h1));
    lv.y = pk2(v.z - __bfloat162float(h2), v.w - __bfloat162float(h3));
    ((uint2*)g_wh)[i] = hv;
    ((uint2*)g_wl)[i] = lv;
}

// ---------------- precompute kernel B: scales (warp per p-row) ----------------
// 16 blocks x 256 threads (8 warps), warp handles row p = blockIdx*8 + wid
__global__ void ds_scales(const float* __restrict__ w,
                          const float* __restrict__ eta,
                          const float* __restrict__ xi,
                          const float* __restrict__ beta) {
    int lane = threadIdx.x & 31;
    int p = blockIdx.x * 8 + (threadIdx.x >> 5);
    float s = 0.f;
    const float4* wr = (const float4*)(w + (size_t)p * F_DIM);
#pragma unroll
    for (int j = 0; j < 4; ++j) {
        float4 v = wr[j * 32 + lane];
        s = fmaf(v.x, v.x, s);
        s = fmaf(v.y, v.y, s);
        s = fmaf(v.z, v.z, s);
        s = fmaf(v.w, v.w, s);
    }
#pragma unroll
    for (int o = 16; o > 0; o >>= 1) s += __shfl_xor_sync(0xffffffffu, s, o);
    // lanes 0..9 compute beta^2; reduce across them
    float b2 = 0.f;
    if (lane < C_DIM) {
        float b = beta[lane * P_DIM + p];
        b2 = b * b;
    }
    float bs = b2;
#pragma unroll
    for (int o = 16; o > 0; o >>= 1) bs += __shfl_xor_sync(0xffffffffu, bs, o);
    if (lane < C_DIM) g_u[lane * P_DIM + p] = b2 / bs;
    if (lane == 0) {
        g_wsq[p] = s;
        float e = eta[p];
        g_gamma[p] = e * e;
        g_alpha[p] = 1.f / (1.f + expf(-xi[p]));
    }
}

// ---------------- smem layout (bytes) ----------------
#define OFF_SXL 36864
#define OFF_SWH 73728
#define OFF_SWL 110592
#define OFF_US  147456
#define OFF_XNS 152576
#define OFF_XNP 153088
#define SMEM_BYTES 154112
#define STAGE_B 18432     // bytes per stage within each array

__global__ void __launch_bounds__(TPB, 1)
ds_main(const float* __restrict__ x, float* __restrict__ out) {
    extern __shared__ char smem[];
    __nv_bfloat16* sxh = (__nv_bfloat16*)(smem);
    __nv_bfloat16* sxl = (__nv_bfloat16*)(smem + OFF_SXL);
    __nv_bfloat16* swh = (__nv_bfloat16*)(smem + OFF_SWH);
    __nv_bfloat16* swl = (__nv_bfloat16*)(smem + OFF_SWL);
    float* si  = (float*)smem;
    float* us  = (float*)(smem + OFF_US);
    float* xns = (float*)(smem + OFF_XNS);
    float* xnp = (float*)(smem + OFF_XNP);
    unsigned sm_u32 = (unsigned)__cvta_generic_to_shared(smem);

    const int tid  = threadIdx.x;
    const int lane = tid & 31;
    const int wid  = tid >> 5;
    const int row0 = blockIdx.x * BM;

    // stage u into smem
    for (int i = tid; i < C_DIM * P_DIM; i += TPB) us[i] = g_u[i];

    // load/convert role: thread owns row r, k-half kh
    const int lr = tid >> 1;
    const int lkh = (tid & 1) * 32;
    const float* xblk = x + (size_t)row0 * F_DIM;

    float acc[2][8][4];
#pragma unroll
    for (int mt = 0; mt < 2; ++mt)
#pragma unroll
        for (int nt = 0; nt < 8; ++nt)
#pragma unroll
            for (int e = 0; e < 4; ++e) acc[mt][nt][e] = 0.f;

    float xn = 0.f;
    float4 xv[8];

    // ---- w tile issue (cp.async) ----
    auto issue_w = [&](int kt, int s) {
        const __nv_bfloat16* sH = g_wh + (size_t)lr * F_DIM + kt * BK + lkh;
        const __nv_bfloat16* sL = g_wl + (size_t)lr * F_DIM + kt * BK + lkh;
        unsigned dH = sm_u32 + OFF_SWH + s * STAGE_B + (lr * PITCH + lkh) * 2;
        unsigned dL = sm_u32 + OFF_SWL + s * STAGE_B + (lr * PITCH + lkh) * 2;
#pragma unroll
        for (int j = 0; j < 4; ++j) {
            cp16(dH + 16 * j, sH + 8 * j);
            cp16(dL + 16 * j, sL + 8 * j);
        }
        cp_commit();
    };
    // ---- x tile global load ----
    auto ldx = [&](int kt) {
        const float* p = xblk + (size_t)lr * F_DIM + kt * BK + lkh;
#pragma unroll
        for (int j = 0; j < 8; ++j) xv[j] = *(const float4*)(p + 4 * j);
    };
    // ---- x tile split/convert + smem store (+ ||x||^2) ----
    auto stx = [&](int s) {
        __nv_bfloat16* dh = sxh + s * (STAGE_B / 2) + lr * PITCH + lkh;
        __nv_bfloat16* dl = sxl + s * (STAGE_B / 2) + lr * PITCH + lkh;
#pragma unroll
        for (int j = 0; j < 8; ++j) {
            float f0 = xv[j].x, f1 = xv[j].y, f2 = xv[j].z, f3 = xv[j].w;
            xn = fmaf(f0, f0, xn); xn = fmaf(f1, f1, xn);
            xn = fmaf(f2, f2, xn); xn = fmaf(f3, f3, xn);
            __nv_bfloat16 h0 = __float2bfloat16_rn(f0), h1 = __float2bfloat16_rn(f1);
            __nv_bfloat16 h2 = __float2bfloat16_rn(f2), h3 = __float2bfloat16_rn(f3);
            uint2 hv, lv;
            hv.x = pk2(f0, f1); hv.y = pk2(f2, f3);
            lv.x = pk2(f0 - __bfloat162float(h0), f1 - __bfloat162float(h1));
            lv.y = pk2(f2 - __bfloat162float(h2), f3 - __bfloat162float(h3));
            *(uint2*)(dh + 4 * j) = hv;
            *(uint2*)(dl + 4 * j) = lv;
        }
    };

    const int wm = (wid & 3) * 32;
    const int wn = (wid >> 2) * 64;
    const int lq  = lane >> 2;
    const int lr2 = (lane & 3) * 2;

    // ---- compute one BK tile from stage s (term-major MMA order for ILP) ----
    auto compute = [&](int s) {
        const __nv_bfloat16* bxh = sxh + s * (STAGE_B / 2);
        const __nv_bfloat16* bxl = sxl + s * (STAGE_B / 2);
        const __nv_bfloat16* bwh = swh + s * (STAGE_B / 2);
        const __nv_bfloat16* bwl = swl + s * (STAGE_B / 2);
#pragma unroll
        for (int kk = 0; kk < BK; kk += 16) {
            unsigned ah[2][4], al[2][4];
#pragma unroll
            for (int mt = 0; mt < 2; ++mt) {
                int base = (wm + mt * 16 + lq) * PITCH + kk + lr2;
                ah[mt][0] = *(const unsigned*)(bxh + base);
                ah[mt][1] = *(const unsigned*)(bxh + base + 8 * PITCH);
                ah[mt][2] = *(const unsigned*)(bxh + base + 8);
                ah[mt][3] = *(const unsigned*)(bxh + base + 8 * PITCH + 8);
                al[mt][0] = *(const unsigned*)(bxl + base);
                al[mt][1] = *(const unsigned*)(bxl + base + 8 * PITCH);
                al[mt][2] = *(const unsigned*)(bxl + base + 8);
                al[mt][3] = *(const unsigned*)(bxl + base + 8 * PITCH + 8);
            }
            unsigned bh[8][2], bl[8][2];
#pragma unroll
            for (int nt = 0; nt < 8; ++nt) {
                int nb = (wn + nt * 8 + lq) * PITCH + kk + lr2;
                bh[nt][0] = *(const unsigned*)(bwh + nb);
                bh[nt][1] = *(const unsigned*)(bwh + nb + 8);
                bl[nt][0] = *(const unsigned*)(bwl + nb);
                bl[nt][1] = *(const unsigned*)(bwl + nb + 8);
            }
            // term 1: hi*hi — 16 independent MMAs
#pragma unroll
            for (int nt = 0; nt < 8; ++nt)
#pragma unroll
                for (int mt = 0; mt < 2; ++mt)
                    mma16816(acc[mt][nt], ah[mt], bh[nt]);
            // term 2: lo*hi
#pragma unroll
            for (int nt = 0; nt < 8; ++nt)
#pragma unroll
                for (int mt = 0; mt < 2; ++mt)
                    mma16816(acc[mt][nt], al[mt], bh[nt]);
            // term 3: hi*lo
#pragma unroll
            for (int nt = 0; nt < 8; ++nt)
#pragma unroll
                for (int mt = 0; mt < 2; ++mt)
                    mma16816(acc[mt][nt], ah[mt], bl[nt]);
        }
    };

    // ---- pipelined main loop ----
    issue_w(0, 0);
    ldx(0);
    stx(0);
    cp_wait0();
    __syncthreads();

    for (int kt = 0; kt < F_DIM / BK; ++kt) {
        int cur = kt & 1;
        if (kt < F_DIM / BK - 1) {
            issue_w(kt + 1, 1 - cur);
            ldx(kt + 1);
        }
        compute(cur);
        if (kt < F_DIM / BK - 1) stx(1 - cur);
        cp_wait0();
        __syncthreads();
    }

    // ---- ||x||^2 reduction ----
    xnp[tid] = xn;
    __syncthreads();
    if (tid < BM) xns[tid] = xnp[2 * tid] + xnp[2 * tid + 1];
    __syncthreads();

    // ---- epilogue: d -> si[p][b] ----
    {
        float xnv[4];
#pragma unroll
        for (int mt = 0; mt < 2; ++mt) {
            xnv[mt * 2 + 0] = xns[wm + mt * 16 + lq];
            xnv[mt * 2 + 1] = xns[wm + mt * 16 + lq + 8];
        }
#pragma unroll
        for (int nt = 0; nt < 8; ++nt) {
            int cb = wn + nt * 8 + lr2;
            float ws0 = g_wsq[cb],   ws1 = g_wsq[cb + 1];
            float ga0 = g_gamma[cb], ga1 = g_gamma[cb + 1];
            float al0 = g_alpha[cb], al1 = g_alpha[cb + 1];
#pragma unroll
            for (int mt = 0; mt < 2; ++mt) {
                int r0 = wm + mt * 16 + lq;
                int r1 = r0 + 8;
                const float* a = acc[mt][nt];
                float d00 = xnv[mt * 2]     + ws0 - 2.f * a[0];
                float d01 = xnv[mt * 2]     + ws1 - 2.f * a[1];
                float d10 = xnv[mt * 2 + 1] + ws0 - 2.f * a[2];
                float d11 = xnv[mt * 2 + 1] + ws1 - 2.f * a[3];
                si[cb * SIP + r0]       = al0 * __expf(-ga0 * d00);
                si[(cb + 1) * SIP + r0] = al1 * __expf(-ga1 * d01);
                si[cb * SIP + r1]       = al0 * __expf(-ga0 * d10);
                si[(cb + 1) * SIP + r1] = al1 * __expf(-ga1 * d11);
            }
        }
    }
    __syncthreads();

    // ---- Dempster scan: one thread per batch row ----
    if (tid < BM) {
        const int r = tid;
        float mx = 0.f;
        for (int p = 0; p < P_DIM; ++p) mx = fmaxf(mx, si[p * SIP + r]);
        const float sinv = 1.f / (mx + 1e-4f);

        float s = si[r] * sinv;
        float m[C_DIM];
#pragma unroll
        for (int k = 0; k < C_DIM; ++k) m[k] = us[k * P_DIM + 0] * s;
        float o = 1.f - s;

        for (int p = 1; p < P_DIM; ++p) {
            s = si[p * SIP + r] * sinv;
            float om = 1.f - s;
            float os = o * s;
#pragma unroll
            for (int k = 0; k < C_DIM; ++k) {
                float u = us[k * P_DIM + p];
                float t = fmaf(s, u, om);        // 1 - s + s*u
                m[k] = fmaf(m[k], t, os * u);
            }
            o = 3.f * o * om;                    // c_omega = 3*o1*o2
            if ((p & 7) == 7) {                  // scale-invariant renorm
                float ssum = o;
#pragma unroll
                for (int k = 0; k < C_DIM; ++k) ssum += m[k];
                float rinv = 1.f / ssum;
#pragma unroll
                for (int k = 0; k < C_DIM; ++k) m[k] *= rinv;
                o *= rinv;
            }
        }
        float ssum = o;
#pragma unroll
        for (int k = 0; k < C_DIM; ++k) ssum += m[k];
        float rinv = 1.f / ssum;
        float* op = out + (size_t)(row0 + r) * (C_DIM + 1);
#pragma unroll
        for (int k = 0; k < C_DIM; ++k) op[k] = m[k] * rinv;
        op[C_DIM] = o * rinv;
    }
}

// ---------------- launch ----------------
extern "C" void kernel_launch(void* const* d_in, const int* in_sizes, int n_in,
                              void* d_out, int out_size) {
    const float* x    = (const float*)d_in[0];
    const float* w    = (const float*)d_in[1];
    const float* eta  = (const float*)d_in[2];
    const float* xi   = (const float*)d_in[3];
    const float* beta = (const float*)d_in[4];
    float* out = (float*)d_out;

    ds_split_w<<<P_DIM * F_DIM / 4 / 256, 256>>>(w);
    ds_scales<<<P_DIM / 8, 256>>>(w, eta, xi, beta);

    cudaFuncSetAttribute(ds_main, cudaFuncAttributeMaxDynamicSharedMemorySize,
                         SMEM_BYTES);
    ds_main<<<B_TOTAL / BM, TPB, SMEM_BYTES>>>(x, out);
}

// round 6
// speedup vs baseline: 1.9783x; 1.1342x over previous
#include <cuda_runtime.h>
#include <cuda_bf16.h>
#include <math.h>
#include <stdint.h>

#define B_TOTAL 16384
#define F_DIM   512
#define P_DIM   128
#define C_DIM   10

#define BM   128
#define BK   64
#define TPB  256
#define PITCH 72          // bf16 pitch of GEMM smem tiles (conflict-free LDSM)
#define SIP  130          // float pitch of si tile

// ---------------- device-global precomputed tensors ----------------
__device__ __align__(16) __nv_bfloat16 g_wh[P_DIM * F_DIM];
__device__ __align__(16) __nv_bfloat16 g_wl[P_DIM * F_DIM];
__device__ float g_wsq[P_DIM];
__device__ float g_gamma[P_DIM];
__device__ float g_alpha[P_DIM];
__device__ float g_u[C_DIM * P_DIM];   // [c][p]

// ---------------- helpers ----------------
__device__ __forceinline__ unsigned pk2(float a, float b) {
    __nv_bfloat162 t;
    t.x = __float2bfloat16_rn(a);
    t.y = __float2bfloat16_rn(b);
    return *reinterpret_cast<unsigned*>(&t);
}

__device__ __forceinline__ void cp16(unsigned dst, const void* src) {
    asm volatile("cp.async.ca.shared.global [%0], [%1], 16;\n" :: "r"(dst), "l"(src));
}
__device__ __forceinline__ void cp_commit() { asm volatile("cp.async.commit_group;\n"); }
__device__ __forceinline__ void cp_wait0()  { asm volatile("cp.async.wait_group 0;\n"); }

__device__ __forceinline__ void ldsm4(unsigned& r0, unsigned& r1, unsigned& r2, unsigned& r3,
                                      unsigned addr) {
    asm volatile("ldmatrix.sync.aligned.m8n8.x4.shared.b16 {%0,%1,%2,%3}, [%4];\n"
                 : "=r"(r0), "=r"(r1), "=r"(r2), "=r"(r3) : "r"(addr));
}

__device__ __forceinline__ void mma16816(float* c, const unsigned* a, const unsigned* b) {
    asm volatile(
        "mma.sync.aligned.m16n8k16.row.col.f32.bf16.bf16.f32 "
        "{%0,%1,%2,%3}, {%4,%5,%6,%7}, {%8,%9}, {%0,%1,%2,%3};\n"
        : "+f"(c[0]), "+f"(c[1]), "+f"(c[2]), "+f"(c[3])
        : "r"(a[0]), "r"(a[1]), "r"(a[2]), "r"(a[3]), "r"(b[0]), "r"(b[1]));
}

// ---------------- fused precompute kernel ----------------
// blocks 0..127: split w (float2 per thread); blocks 128..143: scales
__global__ void ds_precomp(const float* __restrict__ w,
                           const float* __restrict__ eta,
                           const float* __restrict__ xi,
                           const float* __restrict__ beta) {
    if (blockIdx.x < 128) {
        int i = blockIdx.x * 256 + threadIdx.x;   // 0 .. 32767 float2s
        float2 v = ((const float2*)w)[i];
        __nv_bfloat16 h0 = __float2bfloat16_rn(v.x), h1 = __float2bfloat16_rn(v.y);
        ((unsigned*)g_wh)[i] = pk2(v.x, v.y);
        ((unsigned*)g_wl)[i] = pk2(v.x - __bfloat162float(h0), v.y - __bfloat162float(h1));
        return;
    }
    int lane = threadIdx.x & 31;
    int p = (blockIdx.x - 128) * 8 + (threadIdx.x >> 5);
    float s = 0.f;
    const float4* wr = (const float4*)(w + (size_t)p * F_DIM);
#pragma unroll
    for (int j = 0; j < 4; ++j) {
        float4 v = wr[j * 32 + lane];
        s = fmaf(v.x, v.x, s);
        s = fmaf(v.y, v.y, s);
        s = fmaf(v.z, v.z, s);
        s = fmaf(v.w, v.w, s);
    }
#pragma unroll
    for (int o = 16; o > 0; o >>= 1) s += __shfl_xor_sync(0xffffffffu, s, o);
    float b2 = 0.f;
    if (lane < C_DIM) {
        float b = beta[lane * P_DIM + p];
        b2 = b * b;
    }
    float bs = b2;
#pragma unroll
    for (int o = 16; o > 0; o >>= 1) bs += __shfl_xor_sync(0xffffffffu, bs, o);
    if (lane < C_DIM) g_u[lane * P_DIM + p] = b2 / bs;
    if (lane == 0) {
        g_wsq[p] = s;
        float e = eta[p];
        g_gamma[p] = e * e;
        g_alpha[p] = 1.f / (1.f + expf(-xi[p]));
    }
}

// ---------------- smem layout (bytes) ----------------
#define OFF_SXL 36864
#define OFF_SWH 73728
#define OFF_SWL 110592
#define OFF_US  147456
#define OFF_XNS 152576
#define OFF_XNP 153088
#define SMEM_BYTES 154112
#define STAGE_B 18432     // bytes per stage within each array

__global__ void __launch_bounds__(TPB, 1)
ds_main(const float* __restrict__ x, float* __restrict__ out) {
    extern __shared__ char smem[];
    __nv_bfloat16* sxh = (__nv_bfloat16*)(smem);
    __nv_bfloat16* sxl = (__nv_bfloat16*)(smem + OFF_SXL);
    float* si  = (float*)smem;
    float* us  = (float*)(smem + OFF_US);
    float* xns = (float*)(smem + OFF_XNS);
    float* xnp = (float*)(smem + OFF_XNP);
    unsigned sm_u32 = (unsigned)__cvta_generic_to_shared(smem);

    const int tid  = threadIdx.x;
    const int lane = tid & 31;
    const int wid  = tid >> 5;
    const int row0 = blockIdx.x * BM;

    for (int i = tid; i < C_DIM * P_DIM; i += TPB) us[i] = g_u[i];

    const int lr = tid >> 1;
    const int lkh = (tid & 1) * 32;
    const float* xblk = x + (size_t)row0 * F_DIM;

    float acc[2][8][4];
#pragma unroll
    for (int mt = 0; mt < 2; ++mt)
#pragma unroll
        for (int nt = 0; nt < 8; ++nt)
#pragma unroll
            for (int e = 0; e < 4; ++e) acc[mt][nt][e] = 0.f;

    float xn = 0.f;
    float4 xv[8];

    auto issue_w = [&](int kt, int s) {
        const __nv_bfloat16* sH = g_wh + (size_t)lr * F_DIM + kt * BK + lkh;
        const __nv_bfloat16* sL = g_wl + (size_t)lr * F_DIM + kt * BK + lkh;
        unsigned dH = sm_u32 + OFF_SWH + s * STAGE_B + (lr * PITCH + lkh) * 2;
        unsigned dL = sm_u32 + OFF_SWL + s * STAGE_B + (lr * PITCH + lkh) * 2;
#pragma unroll
        for (int j = 0; j < 4; ++j) {
            cp16(dH + 16 * j, sH + 8 * j);
            cp16(dL + 16 * j, sL + 8 * j);
        }
        cp_commit();
    };
    auto ldx = [&](int kt) {
        const float* p = xblk + (size_t)lr * F_DIM + kt * BK + lkh;
#pragma unroll
        for (int j = 0; j < 8; ++j) xv[j] = *(const float4*)(p + 4 * j);
    };
    auto stx = [&](int s) {
        __nv_bfloat16* dh = sxh + s * (STAGE_B / 2) + lr * PITCH + lkh;
        __nv_bfloat16* dl = sxl + s * (STAGE_B / 2) + lr * PITCH + lkh;
#pragma unroll
        for (int j = 0; j < 8; ++j) {
            float f0 = xv[j].x, f1 = xv[j].y, f2 = xv[j].z, f3 = xv[j].w;
            xn = fmaf(f0, f0, xn); xn = fmaf(f1, f1, xn);
            xn = fmaf(f2, f2, xn); xn = fmaf(f3, f3, xn);
            __nv_bfloat16 h0 = __float2bfloat16_rn(f0), h1 = __float2bfloat16_rn(f1);
            __nv_bfloat16 h2 = __float2bfloat16_rn(f2), h3 = __float2bfloat16_rn(f3);
            uint2 hv, lv;
            hv.x = pk2(f0, f1); hv.y = pk2(f2, f3);
            lv.x = pk2(f0 - __bfloat162float(h0), f1 - __bfloat162float(h1));
            lv.y = pk2(f2 - __bfloat162float(h2), f3 - __bfloat162float(h3));
            *(uint2*)(dh + 4 * j) = hv;
            *(uint2*)(dl + 4 * j) = lv;
        }
    };

    const int wm = (wid & 3) * 32;
    const int wn = (wid >> 2) * 64;
    const int lq  = lane >> 2;
    const int lr2 = (lane & 3) * 2;

    // ---- LDSM lane addressing (byte offsets within a stage) ----
    // A (m16k16 .x4): g=lane>>3, i=lane&7
    //   matrices: {rows m..m+7, k}, {m+8.., k}, {m.., k+8}, {m+8.., k+8}
    const int ai = lane & 7;
    const int ag = lane >> 3;
    const int a_row = wm + (ag & 1) * 8 + ai;     // + mt*16
    const int a_col = (ag >> 1) * 8;              // + kk
    const unsigned a_off = (unsigned)((a_row * PITCH + a_col) * 2);
    // B (two n8k16 frags per .x4): matrices {n..n+7,k},{n..,k+8},{n+8..,k},{n+8..,k+8}
    const int b_row = ((ag >> 1) ? 8 : 0) + ai;   // + wn + ntp*16
    const int b_col = (ag & 1) * 8;               // + kk
    const unsigned b_off = (unsigned)((b_row * PITCH + b_col) * 2);

    auto compute = [&](int s) {
        const unsigned xh_b = sm_u32 + s * STAGE_B + a_off;
        const unsigned xl_b = sm_u32 + OFF_SXL + s * STAGE_B + a_off;
        const unsigned wh_b = sm_u32 + OFF_SWH + s * STAGE_B + (wn * PITCH * 2) + b_off;
        const unsigned wl_b = sm_u32 + OFF_SWL + s * STAGE_B + (wn * PITCH * 2) + b_off;
#pragma unroll
        for (int kk = 0; kk < BK; kk += 16) {
            unsigned ah[2][4], al[2][4], bh[8][2], bl[8][2];
#pragma unroll
            for (int mt = 0; mt < 2; ++mt) {
                unsigned d = (unsigned)(mt * 16 * PITCH * 2 + kk * 2);
                ldsm4(ah[mt][0], ah[mt][1], ah[mt][2], ah[mt][3], xh_b + d);
                ldsm4(al[mt][0], al[mt][1], al[mt][2], al[mt][3], xl_b + d);
            }
#pragma unroll
            for (int ntp = 0; ntp < 4; ++ntp) {
                unsigned d = (unsigned)(ntp * 16 * PITCH * 2 + kk * 2);
                ldsm4(bh[2 * ntp][0], bh[2 * ntp][1], bh[2 * ntp + 1][0], bh[2 * ntp + 1][1],
                      wh_b + d);
                ldsm4(bl[2 * ntp][0], bl[2 * ntp][1], bl[2 * ntp + 1][0], bl[2 * ntp + 1][1],
                      wl_b + d);
            }
            // term-major MMA order: 16 independent accumulators per term
#pragma unroll
            for (int nt = 0; nt < 8; ++nt)
#pragma unroll
                for (int mt = 0; mt < 2; ++mt)
                    mma16816(acc[mt][nt], ah[mt], bh[nt]);
#pragma unroll
            for (int nt = 0; nt < 8; ++nt)
#pragma unroll
                for (int mt = 0; mt < 2; ++mt)
                    mma16816(acc[mt][nt], al[mt], bh[nt]);
#pragma unroll
            for (int nt = 0; nt < 8; ++nt)
#pragma unroll
                for (int mt = 0; mt < 2; ++mt)
                    mma16816(acc[mt][nt], ah[mt], bl[nt]);
        }
    };

    // ---- pipelined main loop ----
    issue_w(0, 0);
    ldx(0);
    stx(0);
    cp_wait0();
    __syncthreads();

    for (int kt = 0; kt < F_DIM / BK; ++kt) {
        int cur = kt & 1;
        if (kt < F_DIM / BK - 1) {
            issue_w(kt + 1, 1 - cur);
            ldx(kt + 1);
        }
        compute(cur);
        if (kt < F_DIM / BK - 1) stx(1 - cur);
        cp_wait0();
        __syncthreads();
    }

    // ---- ||x||^2 reduction ----
    xnp[tid] = xn;
    __syncthreads();
    if (tid < BM) xns[tid] = xnp[2 * tid] + xnp[2 * tid + 1];
    __syncthreads();

    // ---- epilogue: d -> si[p][b] ----
    {
        float xnv[4];
#pragma unroll
        for (int mt = 0; mt < 2; ++mt) {
            xnv[mt * 2 + 0] = xns[wm + mt * 16 + lq];
            xnv[mt * 2 + 1] = xns[wm + mt * 16 + lq + 8];
        }
#pragma unroll
        for (int nt = 0; nt < 8; ++nt) {
            int cb = wn + nt * 8 + lr2;
            float ws0 = g_wsq[cb],   ws1 = g_wsq[cb + 1];
            float ga0 = g_gamma[cb], ga1 = g_gamma[cb + 1];
            float al0 = g_alpha[cb], al1 = g_alpha[cb + 1];
#pragma unroll
            for (int mt = 0; mt < 2; ++mt) {
                int r0 = wm + mt * 16 + lq;
                int r1 = r0 + 8;
                const float* a = acc[mt][nt];
                float d00 = xnv[mt * 2]     + ws0 - 2.f * a[0];
                float d01 = xnv[mt * 2]     + ws1 - 2.f * a[1];
                float d10 = xnv[mt * 2 + 1] + ws0 - 2.f * a[2];
                float d11 = xnv[mt * 2 + 1] + ws1 - 2.f * a[3];
                si[cb * SIP + r0]       = al0 * __expf(-ga0 * d00);
                si[(cb + 1) * SIP + r0] = al1 * __expf(-ga1 * d01);
                si[cb * SIP + r1]       = al0 * __expf(-ga0 * d10);
                si[(cb + 1) * SIP + r1] = al1 * __expf(-ga1 * d11);
            }
        }
    }
    __syncthreads();

    // ---- Dempster scan: one thread per batch row ----
    if (tid < BM) {
        const int r = tid;
        float mx = 0.f;
        for (int p = 0; p < P_DIM; ++p) mx = fmaxf(mx, si[p * SIP + r]);
        const float sinv = 1.f / (mx + 1e-4f);

        float s = si[r] * sinv;
        float m[C_DIM];
#pragma unroll
        for (int k = 0; k < C_DIM; ++k) m[k] = us[k * P_DIM + 0] * s;
        float o = 1.f - s;

        for (int p = 1; p < P_DIM; ++p) {
            s = si[p * SIP + r] * sinv;
            float om = 1.f - s;
            float os = o * s;
#pragma unroll
            for (int k = 0; k < C_DIM; ++k) {
                float u = us[k * P_DIM + p];
                float t = fmaf(s, u, om);        // 1 - s + s*u
                m[k] = fmaf(m[k], t, os * u);
            }
            o = 3.f * o * om;                    // c_omega = 3*o1*o2
            if ((p & 7) == 7) {
                float ssum = o;
#pragma unroll
                for (int k = 0; k < C_DIM; ++k) ssum += m[k];
                float rinv = 1.f / ssum;
#pragma unroll
                for (int k = 0; k < C_DIM; ++k) m[k] *= rinv;
                o *= rinv;
            }
        }
        float ssum = o;
#pragma unroll
        for (int k = 0; k < C_DIM; ++k) ssum += m[k];
        float rinv = 1.f / ssum;
        float* op = out + (size_t)(row0 + r) * (C_DIM + 1);
#pragma unroll
        for (int k = 0; k < C_DIM; ++k) op[k] = m[k] * rinv;
        op[C_DIM] = o * rinv;
    }
}

// ---------------- launch ----------------
extern "C" void kernel_launch(void* const* d_in, const int* in_sizes, int n_in,
                              void* d_out, int out_size) {
    const float* x    = (const float*)d_in[0];
    const float* w    = (const float*)d_in[1];
    const float* eta  = (const float*)d_in[2];
    const float* xi   = (const float*)d_in[3];
    const float* beta = (const float*)d_in[4];
    float* out = (float*)d_out;

    ds_precomp<<<144, 256>>>(w, eta, xi, beta);

    cudaFuncSetAttribute(ds_main, cudaFuncAttributeMaxDynamicSharedMemorySize,
                         SMEM_BYTES);
    ds_main<<<B_TOTAL / BM, TPB, SMEM_BYTES>>>(x, out);
}